// round 7
// baseline (speedup 1.0000x reference)
#include <cuda_runtime.h>
#include <stdint.h>

// B = 1048576, D = 3, L = 16, C = 2, H = 16, S = 1.0
//   res(l) = 16 << l, side = res+1; dense l=0,1,2; hashed l>=3 (hm = 2^19)
//   offsets: 0, 4920, 40864, 315496, then +524288/level (all even)
//   table = concat(ext[524288,2], own[.,2])
//
// R7: R3's uniform load shape (per x-corner pair: one unconditional aligned
// LDG.128 at a&~1 covering corner a (+ corner b iff (a^b)==1), plus one
// PREDICATED LDG.64 for b on unpaired lanes) -> 8 mem instructions, no
// divergent arms, same sector/wavefront count as R2. Register fix vs R3:
// pairs processed in two chunks of 2 (12 live data regs instead of 24) so
// occupancy returns to R2 levels.

#define HASH_SPLIT 524288u
#define P2 2654435761u
#define P3 805459861u

__device__ __forceinline__ const float2* tptr(unsigned g,
                                              const float2* __restrict__ ext,
                                              const float2* __restrict__ own)
{
    return (g < HASH_SPLIT) ? (ext + g) : (own + (g - HASH_SPLIT));
}

__global__ void __launch_bounds__(256)
grid_encode_kernel(const float* __restrict__ pts,
                   const float2* __restrict__ ext,
                   const float2* __restrict__ own,
                   float2* __restrict__ out)
{
    const unsigned gtid = blockIdx.x * 256u + threadIdx.x;
    const unsigned b = gtid >> 4;
    const unsigned l = gtid & 15u;

    const float px_in = __ldg(&pts[3u * b + 0u]);
    const float py_in = __ldg(&pts[3u * b + 1u]);
    const float pz_in = __ldg(&pts[3u * b + 2u]);

    const unsigned res  = 16u << l;
    const float scale   = (float)(res - 1u);
    const unsigned side = res + 1u;

    const float posx = (px_in + 1.0f) * 0.5f * scale + 0.5f;
    const float posy = (py_in + 1.0f) * 0.5f * scale + 0.5f;
    const float posz = (pz_in + 1.0f) * 0.5f * scale + 0.5f;

    const float flx = floorf(posx);
    const float fly = floorf(posy);
    const float flz = floorf(posz);
    const float fx = posx - flx;
    const float fy = posy - fly;
    const float fz = posz - flz;
    const unsigned x0 = (unsigned)flx;
    const unsigned y0 = (unsigned)fly;
    const unsigned z0 = (unsigned)flz;

    const bool hashed = (l >= 3u);
    const unsigned off = hashed ? (315496u + (l - 3u) * 524288u)
                                : (l == 0u ? 0u : (l == 1u ? 4920u : 40864u));

    // Per-axis terms. Hash: uint32 wraparound, PRIMES = {1, P2, P3}.
    const unsigned hy0 = y0 * P2;
    const unsigned hz0 = z0 * P3;
    const unsigned hys[2] = { hy0, hy0 + P2 };
    const unsigned hzs[2] = { hz0, hz0 + P3 };
    // Dense: no modulo needed (side^3 <= hm for l<=2).
    const unsigned side2 = side * side;
    const unsigned dys[2] = { y0 * side,  y0 * side + side };
    const unsigned dzs[2] = { z0 * side2, z0 * side2 + side2 };

    const float wx0 = 1.0f - fx, wx1 = fx;
    const float wyv[2] = { 1.0f - fy, fy };
    const float wzv[2] = { 1.0f - fz, fz };

    float accx = 0.0f, accy = 0.0f;

    // Two chunks of two (y,z) pairs each: keeps live data regs at 12.
#pragma unroll
    for (int chunk = 0; chunk < 2; ++chunk) {
        unsigned ia[2], ib[2];
#pragma unroll
        for (int j = 0; j < 2; ++j) {
            const int q = chunk * 2 + j;
            const int cy = q & 1, cz = (q >> 1) & 1;
            unsigned a, bx;
            if (hashed) {
                const unsigned hb = hys[cy] ^ hzs[cz];
                a  = (x0 ^ hb) & (HASH_SPLIT - 1u);
                bx = ((x0 + 1u) ^ hb) & (HASH_SPLIT - 1u);
            } else {
                const unsigned db = dys[cy] + dzs[cz];
                a  = x0 + db;
                bx = a + 1u;
            }
            ia[j] = off + a;
            ib[j] = off + bx;
        }

        // Unconditional aligned LDG.128: always contains corner a; contains
        // corner b too iff (ia^ib)==1. [a&~1, a&~1+1] never crosses a level
        // or ext/own boundary (all offsets/sizes even).
        float4 w4[2];
#pragma unroll
        for (int j = 0; j < 2; ++j)
            w4[j] = __ldg((const float4*)tptr(ia[j] & ~1u, ext, own));

        // Predicated LDG.64 for corner b on unpaired lanes only.
        float2 vb[2];
#pragma unroll
        for (int j = 0; j < 2; ++j) {
            vb[j] = make_float2(0.0f, 0.0f);
            if ((ia[j] ^ ib[j]) != 1u)
                vb[j] = __ldg(tptr(ib[j], ext, own));
        }

        // Branchless select + accumulate.
#pragma unroll
        for (int j = 0; j < 2; ++j) {
            const int q = chunk * 2 + j;
            const bool paired = ((ia[j] ^ ib[j]) == 1u);
            const bool ahi = (ia[j] & 1u);
            const float vax = ahi ? w4[j].z : w4[j].x;
            const float vay = ahi ? w4[j].w : w4[j].y;
            const float pbx = ahi ? w4[j].x : w4[j].z;
            const float pby = ahi ? w4[j].y : w4[j].w;
            const float vbx = paired ? pbx : vb[j].x;
            const float vby = paired ? pby : vb[j].y;

            const int cy = q & 1, cz = (q >> 1) & 1;
            const float wyz = wyv[cy] * wzv[cz];
            accx += wyz * (wx0 * vax + wx1 * vbx);
            accy += wyz * (wx0 * vay + wx1 * vby);
        }
    }

    out[gtid] = make_float2(accx, accy);
}

extern "C" void kernel_launch(void* const* d_in, const int* in_sizes, int n_in,
                              void* d_out, int out_size)
{
    const float*  pts = (const float*)d_in[0];        // [B, 3]
    const float2* ext = (const float2*)d_in[1];       // [524288, 2]
    const float2* own = (const float2*)d_in[2];       // [N_TABLE - 524288, 2]
    float2* out = (float2*)d_out;                     // [B*16] float2

    grid_encode_kernel<<<65536, 256>>>(pts, ext, own, out);
}